// round 4
// baseline (speedup 1.0000x reference)
#include <cuda_runtime.h>
#include <math_constants.h>
#include <cstdint>

// Shapes (fixed):
//   word_features  [B, D, T]   = [32, 256, 32]   fp32   d_in[0]
//   image_features [B, Dh,H,W] = [32, 128,128,128] fp32 d_in[1]
//   words_mask     [B, T]      = [32, 32]        int32  d_in[2]
//   W              [Dh, D]     = [128, 256]      fp32   d_in[3]
//   b              [Dh]        = [128]           fp32   d_in[4]
// Outputs: attn [B,Dh,N] at 0, attn_coefficients [B,N,T] at B*Dh*N.

#define B_   32
#define D_   256
#define T_   32
#define DH_  128
#define N_   16384

__device__ float g_values[B_ * DH_ * T_];

// ---------------- packed f32x2 helpers ----------------
__device__ __forceinline__ unsigned long long pk2(float lo, float hi) {
    unsigned long long r;
    asm("mov.b64 %0, {%1, %2};" : "=l"(r) : "f"(lo), "f"(hi));
    return r;
}
__device__ __forceinline__ float2 unpk2(unsigned long long v) {
    float2 f;
    asm("mov.b64 {%0, %1}, %2;" : "=f"(f.x), "=f"(f.y) : "l"(v));
    return f;
}
__device__ __forceinline__ unsigned long long ffma2(unsigned long long a,
                                                    unsigned long long b,
                                                    unsigned long long c) {
    unsigned long long d;
    asm("fma.rn.f32x2 %0, %1, %2, %3;" : "=l"(d) : "l"(a), "l"(b), "l"(c));
    return d;
}

// ---------------- kernel 1: values = W * wf + b ----------------
// grid = B, block = 256. Thread = (k = tid/2, half = tid&1): computes 16 t's
// of row k with packed f32x2.
__global__ __launch_bounds__(256)
void values_kernel(const float* __restrict__ wf,
                   const float* __restrict__ Wm,
                   const float* __restrict__ bias) {
    __shared__ float swf[D_ * T_];  // 32 KB, [d][t]
    const int b = blockIdx.x;
    const int tid = threadIdx.x;
    const int k = tid >> 1;
    const int half = tid & 1;

    {
        const float4* src =
            reinterpret_cast<const float4*>(wf + (size_t)b * D_ * T_);
        float4* dst = reinterpret_cast<float4*>(swf);
        for (int i = tid; i < D_ * T_ / 4; i += 256) dst[i] = src[i];
    }
    __syncthreads();

    const float bk = bias[k];
    unsigned long long acc[8];
#pragma unroll
    for (int j = 0; j < 8; j++) acc[j] = pk2(bk, bk);

    const float4* wr = reinterpret_cast<const float4*>(Wm + (size_t)k * D_);
#pragma unroll 2
    for (int d4 = 0; d4 < D_ / 4; d4++) {
        const float4 w = wr[d4];
        const float wv[4] = {w.x, w.y, w.z, w.w};
#pragma unroll
        for (int s = 0; s < 4; s++) {
            const unsigned long long wp = pk2(wv[s], wv[s]);
            const ulonglong2* vr = reinterpret_cast<const ulonglong2*>(
                &swf[(4 * d4 + s) * T_ + half * 16]);
#pragma unroll
            for (int j = 0; j < 2; j++) {
                const ulonglong2 v = vr[j];
                acc[4 * j + 0] = ffma2(wp, v.x, acc[4 * j + 0]);
                acc[4 * j + 1] = ffma2(wp, v.y, acc[4 * j + 1]);
            }
        }
    }
    // NOTE: packing above: vr[j].x covers t-pairs (8j..) — keep memory order:
    // acc index mapping: acc[4j+0] = pair (8j+0,8j+1)? Rebuild in memory order:
    // We stored per j: v.x (floats 8j..8j+1? no: ulonglong2 = 4 floats).
    // vr[j] = floats [8j .. 8j+3] of the 16-float slice: v.x = (8j,8j+1),
    // v.y = (8j+2,8j+3). acc[4j+0] ~ (8j,8j+1), acc[4j+1] ~ (8j+2,8j+3).
    // Remaining pairs (8j+4..8j+7) handled by second vr element:
    // (covered since j loop is 0..1 over 2 ulonglong2 = 16 floats, and we
    // use acc[4j+0..1]; acc[4j+2..3] unused — fix: use 4 floats per j only.)
    {
        // write 16 floats: acc[0],acc[1] are j=0 pairs (t 0..3),
        // acc[4],acc[5] are j=1 pairs (t 8..11). We must also cover t 4..7 and
        // t 12..15 — reorganize: redo with explicit 4-ulonglong2 row view.
    }
    float* outp = g_values + ((size_t)b * DH_ + k) * T_ + half * 16;
    // Correct, simple recompute-free store is only valid if mapping is right;
    // instead of the ambiguous packing above, we recompute cleanly below.
    // (See corrected loop — the loop above is replaced by this one.)
    // -- corrected accumulation --
#pragma unroll
    for (int j = 0; j < 8; j++) acc[j] = pk2(bk, bk);
#pragma unroll 2
    for (int d = 0; d < D_; d++) {
        const float wsc = Wm[(size_t)k * D_ + d];
        const unsigned long long wp = pk2(wsc, wsc);
        const ulonglong2* vr = reinterpret_cast<const ulonglong2*>(
            &swf[d * T_ + half * 16]);
#pragma unroll
        for (int j = 0; j < 4; j++) {
            const ulonglong2 v = vr[j];
            acc[2 * j + 0] = ffma2(wp, v.x, acc[2 * j + 0]);
            acc[2 * j + 1] = ffma2(wp, v.y, acc[2 * j + 1]);
        }
    }
    ulonglong2* o2 = reinterpret_cast<ulonglong2*>(outp);
#pragma unroll
    for (int j = 0; j < 4; j++) {
        ulonglong2 v;
        v.x = acc[2 * j + 0];
        v.y = acc[2 * j + 1];
        o2[j] = v;
    }
}

// ---------------- kernel 2: scores + softmax + context ----------------
// block = 256 (8 warps). Lane pair (2p, 2p+1) shares pixels n0, n0+1;
// even lane owns t[0..15], odd lane owns t[16..31]. Warp covers 32 pixels,
// block covers 256. grid = (N/256, B).
__global__ __launch_bounds__(256, 3)
void attn_kernel(const float* __restrict__ img,
                 const int* __restrict__ mask,
                 float* __restrict__ out_attn,
                 float* __restrict__ out_coef) {
    __shared__ ulonglong2 svals[DH_ * T_ / 4];  // values[b]: [Dh][T] packed
    __shared__ float sneg[T_];                  // -inf where masked, else 0

    const int b = blockIdx.y;
    const int tid = threadIdx.x;
    const int lane = tid & 31;
    const int warp = tid >> 5;
    const int half = lane & 1;
    const int pair = lane >> 1;
    const int n0 = blockIdx.x * 256 + warp * 32 + pair * 2;

    {
        const ulonglong2* gv = reinterpret_cast<const ulonglong2*>(
            g_values + (size_t)b * DH_ * T_);
        for (int i = tid; i < DH_ * T_ / 4; i += 256) svals[i] = gv[i];
        if (tid < T_)
            sneg[tid] = (mask[b * T_ + tid] != 0) ? -CUDART_INF_F : 0.0f;
    }
    __syncthreads();

    const int vofs = half * 4;  // ulonglong2 offset of this lane's t-half

    // ---- phase 1: S[px][t_half] = sum_k q[px][k] * vals[k][t_half] ----
    unsigned long long acc[2][8];
#pragma unroll
    for (int px = 0; px < 2; px++)
#pragma unroll
        for (int j = 0; j < 8; j++) acc[px][j] = 0ULL;

    const float2* qb =
        reinterpret_cast<const float2*>(img + (size_t)b * DH_ * N_ + n0);

    float2 qv[4];
#pragma unroll
    for (int kk = 0; kk < 4; kk++) qv[kk] = qb[(size_t)kk * (N_ / 2)];

    for (int k = 0; k < DH_; k += 4) {
        float2 qn[4];
        if (k + 4 < DH_) {
#pragma unroll
            for (int kk = 0; kk < 4; kk++)
                qn[kk] = qb[(size_t)(k + 4 + kk) * (N_ / 2)];
        }
#pragma unroll
        for (int kk = 0; kk < 4; kk++) {
            const unsigned long long q0 = pk2(qv[kk].x, qv[kk].x);
            const unsigned long long q1 = pk2(qv[kk].y, qv[kk].y);
            const ulonglong2* vr = &svals[(k + kk) * 8 + vofs];
#pragma unroll
            for (int j = 0; j < 4; j++) {
                const ulonglong2 v = vr[j];
                acc[0][2 * j + 0] = ffma2(q0, v.x, acc[0][2 * j + 0]);
                acc[0][2 * j + 1] = ffma2(q0, v.y, acc[0][2 * j + 1]);
                acc[1][2 * j + 0] = ffma2(q1, v.x, acc[1][2 * j + 0]);
                acc[1][2 * j + 1] = ffma2(q1, v.y, acc[1][2 * j + 1]);
            }
        }
#pragma unroll
        for (int kk = 0; kk < 4; kk++) qv[kk] = qn[kk];
    }

    // ---- phase 2: masked softmax (pair-cooperative over t) ----
#pragma unroll
    for (int px = 0; px < 2; px++) {
        float Sv[16];
#pragma unroll
        for (int j = 0; j < 8; j++) {
            float2 f = unpk2(acc[px][j]);
            Sv[2 * j + 0] = f.x;
            Sv[2 * j + 1] = f.y;
        }
        float m = -CUDART_INF_F;
#pragma unroll
        for (int i = 0; i < 16; i++) {
            Sv[i] += sneg[half * 16 + i];
            m = fmaxf(m, Sv[i]);
        }
        m = fmaxf(m, __shfl_xor_sync(0xffffffffu, m, 1));
        float sum = 0.f;
#pragma unroll
        for (int i = 0; i < 16; i++) {
            Sv[i] = __expf(Sv[i] - m);
            sum += Sv[i];
        }
        sum += __shfl_xor_sync(0xffffffffu, sum, 1);
        const float inv = 1.0f / sum;
#pragma unroll
        for (int i = 0; i < 16; i++) Sv[i] *= inv;

        float4* oc = reinterpret_cast<float4*>(
            out_coef + ((size_t)b * N_ + n0 + px) * T_ + half * 16);
#pragma unroll
        for (int j = 0; j < 4; j++) {
            float4 v;
            v.x = Sv[4 * j + 0];
            v.y = Sv[4 * j + 1];
            v.z = Sv[4 * j + 2];
            v.w = Sv[4 * j + 3];
            oc[j] = v;
        }
#pragma unroll
        for (int j = 0; j < 8; j++)
            acc[px][j] = pk2(Sv[2 * j], Sv[2 * j + 1]);
    }

    // ---- phase 3: attn[px][k] = sum_t vals[k][t] * p[px][t] ----
    float* oa = out_attn + (size_t)b * DH_ * N_ + n0;
#pragma unroll 2
    for (int k = 0; k < DH_; k++) {
        const ulonglong2* vr = &svals[k * 8 + vofs];
        unsigned long long a0A = 0ULL, a0B = 0ULL;
        unsigned long long a1A = 0ULL, a1B = 0ULL;
#pragma unroll
        for (int j = 0; j < 4; j++) {
            const ulonglong2 v = vr[j];
            a0A = ffma2(v.x, acc[0][2 * j + 0], a0A);
            a0B = ffma2(v.y, acc[0][2 * j + 1], a0B);
            a1A = ffma2(v.x, acc[1][2 * j + 0], a1A);
            a1B = ffma2(v.y, acc[1][2 * j + 1], a1B);
        }
        float t0, t1;
        {
            float2 fA = unpk2(a0A), fB = unpk2(a0B);
            t0 = (fA.x + fB.x) + (fA.y + fB.y);
        }
        {
            float2 fA = unpk2(a1A), fB = unpk2(a1B);
            t1 = (fA.x + fB.x) + (fA.y + fB.y);
        }
        t0 += __shfl_xor_sync(0xffffffffu, t0, 1);
        t1 += __shfl_xor_sync(0xffffffffu, t1, 1);
        if ((k & 1) == half) {
            float2 r;
            r.x = t0;
            r.y = t1;
            *reinterpret_cast<float2*>(oa + (size_t)k * N_) = r;
        }
    }
}

extern "C" void kernel_launch(void* const* d_in, const int* in_sizes, int n_in,
                              void* d_out, int out_size) {
    const float* wf   = (const float*)d_in[0];
    const float* img  = (const float*)d_in[1];
    const int*   msk  = (const int*)d_in[2];
    const float* Wm   = (const float*)d_in[3];
    const float* bias = (const float*)d_in[4];

    float* out_attn = (float*)d_out;
    float* out_coef = (float*)d_out + (size_t)B_ * DH_ * N_;

    values_kernel<<<B_, 256>>>(wf, Wm, bias);

    dim3 grid(N_ / 256, B_);
    attn_kernel<<<grid, 256>>>(img, msk, out_attn, out_coef);
}

// round 5
// speedup vs baseline: 1.2321x; 1.2321x over previous
#include <cuda_runtime.h>
#include <math_constants.h>
#include <cstdint>

// Shapes (fixed):
//   word_features  [B, D, T]   = [32, 256, 32]   fp32   d_in[0]
//   image_features [B, Dh,H,W] = [32, 128,128,128] fp32 d_in[1]
//   words_mask     [B, T]      = [32, 32]        int32  d_in[2]
//   W              [Dh, D]     = [128, 256]      fp32   d_in[3]
//   b              [Dh]        = [128]           fp32   d_in[4]
// Outputs: attn [B,Dh,N] at 0, attn_coefficients [B,N,T] at B*Dh*N.

#define B_   32
#define D_   256
#define T_   32
#define DH_  128
#define N_   16384

__device__ float g_values[B_ * DH_ * T_];

// ---------------- packed f32x2 helpers ----------------
__device__ __forceinline__ unsigned long long pk2(float lo, float hi) {
    unsigned long long r;
    asm("mov.b64 %0, {%1, %2};" : "=l"(r) : "f"(lo), "f"(hi));
    return r;
}
__device__ __forceinline__ float2 unpk2(unsigned long long v) {
    float2 f;
    asm("mov.b64 {%0, %1}, %2;" : "=f"(f.x), "=f"(f.y) : "l"(v));
    return f;
}
__device__ __forceinline__ unsigned long long ffma2(unsigned long long a,
                                                    unsigned long long b,
                                                    unsigned long long c) {
    unsigned long long d;
    asm("fma.rn.f32x2 %0, %1, %2, %3;" : "=l"(d) : "l"(a), "l"(b), "l"(c));
    return d;
}

// ---------------- kernel 1: values = W * wf + b ----------------
// grid = (4, B), block = 256. CTA c handles k in [32c, 32c+32).
// thread = (k_local = tid/8, tq = tid%8): 4 t's, 2 packed accumulators.
#define SW_PAD 264
__global__ __launch_bounds__(256)
void values_kernel(const float* __restrict__ wf,
                   const float* __restrict__ Wm,
                   const float* __restrict__ bias) {
    __shared__ float swf[D_ * T_];       // 32 KB  [d][t]
    __shared__ float sW[32 * SW_PAD];    // 33 KB  [k_local][d] padded
    const int c = blockIdx.x;
    const int b = blockIdx.y;
    const int tid = threadIdx.x;

    {
        const float4* src =
            reinterpret_cast<const float4*>(wf + (size_t)b * D_ * T_);
        float4* dst = reinterpret_cast<float4*>(swf);
#pragma unroll
        for (int i = 0; i < 8; i++) dst[tid + 256 * i] = src[tid + 256 * i];

        const float4* wsrc =
            reinterpret_cast<const float4*>(Wm + (size_t)c * 32 * D_);
#pragma unroll
        for (int i = 0; i < 8; i++) {
            const int idx = tid + 256 * i;      // float4 index in 32x256
            const int kl = idx >> 6;            // 64 float4 per row
            const int dc = idx & 63;
            float4 v = wsrc[idx];
            *reinterpret_cast<float4*>(&sW[kl * SW_PAD + dc * 4]) = v;
        }
    }
    __syncthreads();

    const int k_l = tid >> 3;
    const int tq = tid & 7;
    const int k = c * 32 + k_l;

    const float bk = bias[k];
    unsigned long long acc0 = pk2(bk, bk);
    unsigned long long acc1 = pk2(bk, bk);

#pragma unroll 4
    for (int d = 0; d < D_; d++) {
        const float w = sW[k_l * SW_PAD + d];
        const unsigned long long wp = pk2(w, w);
        const ulonglong2 v =
            *reinterpret_cast<const ulonglong2*>(&swf[d * T_ + tq * 4]);
        acc0 = ffma2(wp, v.x, acc0);
        acc1 = ffma2(wp, v.y, acc1);
    }

    ulonglong2 o;
    o.x = acc0;
    o.y = acc1;
    *reinterpret_cast<ulonglong2*>(
        g_values + ((size_t)b * DH_ + k) * T_ + tq * 4) = o;
}

// ---------------- kernel 2: scores + softmax + context ----------------
// block = 256 (8 warps), grid = (N/512, B).
// Lane pair (2p, 2p+1) shares 4 pixels n0..n0+3; even lane owns t[0:16],
// odd lane t[16:32] in phase 1/2. After a one-time pair exchange, even lane
// finishes pixels n0,n0+1 and odd lane n0+2,n0+3 with full t in phase 3.
__global__ __launch_bounds__(256, 2)
void attn_kernel(const float* __restrict__ img,
                 const int* __restrict__ mask,
                 float* __restrict__ out_attn,
                 float* __restrict__ out_coef) {
    __shared__ ulonglong2 svals[DH_ * T_ / 4];  // values[b]: [Dh][T] packed
    __shared__ float sneg[T_];                  // -inf where masked, else 0

    const int b = blockIdx.y;
    const int tid = threadIdx.x;
    const int lane = tid & 31;
    const int warp = tid >> 5;
    const int half = lane & 1;
    const int pair = lane >> 1;
    const int n0 = blockIdx.x * 512 + warp * 64 + pair * 4;

    {
        const ulonglong2* gv = reinterpret_cast<const ulonglong2*>(
            g_values + (size_t)b * DH_ * T_);
#pragma unroll
        for (int i = 0; i < 4; i++) svals[tid + 256 * i] = gv[tid + 256 * i];
        if (tid < T_)
            sneg[tid] = (mask[b * T_ + tid] != 0) ? -CUDART_INF_F : 0.0f;
    }
    __syncthreads();

    // ---- phase 1: S[px][t_half] = sum_k q[px][k] * vals[k][t_half] ----
    unsigned long long acc[4][8];
#pragma unroll
    for (int px = 0; px < 4; px++)
#pragma unroll
        for (int j = 0; j < 8; j++) acc[px][j] = 0ULL;

    const float4* qb =
        reinterpret_cast<const float4*>(img + (size_t)b * DH_ * N_ + n0);

    float4 qv[4];
#pragma unroll
    for (int kk = 0; kk < 4; kk++) qv[kk] = qb[(size_t)kk * (N_ / 4)];

    for (int k = 0; k < DH_; k += 4) {
        float4 qn[4];
        if (k + 4 < DH_) {
#pragma unroll
            for (int kk = 0; kk < 4; kk++)
                qn[kk] = qb[(size_t)(k + 4 + kk) * (N_ / 4)];
        }
#pragma unroll
        for (int kk = 0; kk < 4; kk++) {
            const unsigned long long q0 = pk2(qv[kk].x, qv[kk].x);
            const unsigned long long q1 = pk2(qv[kk].y, qv[kk].y);
            const unsigned long long q2 = pk2(qv[kk].z, qv[kk].z);
            const unsigned long long q3 = pk2(qv[kk].w, qv[kk].w);
            const ulonglong2* vr = &svals[(k + kk) * 8 + half * 4];
#pragma unroll
            for (int j = 0; j < 4; j++) {
                const ulonglong2 v = vr[j];
                acc[0][2 * j + 0] = ffma2(q0, v.x, acc[0][2 * j + 0]);
                acc[0][2 * j + 1] = ffma2(q0, v.y, acc[0][2 * j + 1]);
                acc[1][2 * j + 0] = ffma2(q1, v.x, acc[1][2 * j + 0]);
                acc[1][2 * j + 1] = ffma2(q1, v.y, acc[1][2 * j + 1]);
                acc[2][2 * j + 0] = ffma2(q2, v.x, acc[2][2 * j + 0]);
                acc[2][2 * j + 1] = ffma2(q2, v.y, acc[2][2 * j + 1]);
                acc[3][2 * j + 0] = ffma2(q3, v.x, acc[3][2 * j + 0]);
                acc[3][2 * j + 1] = ffma2(q3, v.y, acc[3][2 * j + 1]);
            }
        }
#pragma unroll
        for (int kk = 0; kk < 4; kk++) qv[kk] = qn[kk];
    }

    // ---- phase 2: masked softmax (pair-cooperative over t) ----
#pragma unroll
    for (int px = 0; px < 4; px++) {
        float Sv[16];
#pragma unroll
        for (int j = 0; j < 8; j++) {
            float2 f = unpk2(acc[px][j]);
            Sv[2 * j + 0] = f.x;
            Sv[2 * j + 1] = f.y;
        }
        float m = -CUDART_INF_F;
#pragma unroll
        for (int i = 0; i < 16; i++) {
            Sv[i] += sneg[half * 16 + i];
            m = fmaxf(m, Sv[i]);
        }
        m = fmaxf(m, __shfl_xor_sync(0xffffffffu, m, 1));
        float sum = 0.f;
#pragma unroll
        for (int i = 0; i < 16; i++) {
            Sv[i] = __expf(Sv[i] - m);
            sum += Sv[i];
        }
        sum += __shfl_xor_sync(0xffffffffu, sum, 1);
        const float inv = 1.0f / sum;
#pragma unroll
        for (int i = 0; i < 16; i++) Sv[i] *= inv;

        float4* oc = reinterpret_cast<float4*>(
            out_coef + ((size_t)b * N_ + n0 + px) * T_ + half * 16);
#pragma unroll
        for (int j = 0; j < 4; j++) {
            float4 v;
            v.x = Sv[4 * j + 0];
            v.y = Sv[4 * j + 1];
            v.z = Sv[4 * j + 2];
            v.w = Sv[4 * j + 3];
            oc[j] = v;
        }
#pragma unroll
        for (int j = 0; j < 8; j++)
            acc[px][j] = pk2(Sv[2 * j], Sv[2 * j + 1]);
    }

    // ---- pair exchange: even lane keeps px0,1 full-t; odd keeps px2,3 ----
    // own[i]  = this lane's t-half of its kept pixel i
    // recv[i] = partner's t-half of the kept pixel i (other half of t)
    unsigned long long own[2][8], recv[2][8];
#pragma unroll
    for (int i = 0; i < 2; i++) {
#pragma unroll
        for (int j = 0; j < 8; j++) {
            const unsigned long long sent =
                half ? acc[i][j] : acc[2 + i][j];          // for partner
            own[i][j] = half ? acc[2 + i][j] : acc[i][j];  // kept px
            recv[i][j] = __shfl_xor_sync(0xffffffffu, sent, 1);
        }
    }

    // ---- phase 3: attn[px][k] = sum_t vals[k][t] * p[px][t] ----
    // own covers t-range [half*16, half*16+16), recv the other half.
    float* oa = out_attn + (size_t)b * DH_ * N_ + n0 + 2 * half;
#pragma unroll 2
    for (int k = 0; k < DH_; k++) {
        const ulonglong2* vO = &svals[k * 8 + half * 4];
        const ulonglong2* vR = &svals[k * 8 + 4 - half * 4];
        unsigned long long a0A = 0ULL, a0B = 0ULL;
        unsigned long long a1A = 0ULL, a1B = 0ULL;
#pragma unroll
        for (int j = 0; j < 4; j++) {
            const ulonglong2 v = vO[j];
            a0A = ffma2(v.x, own[0][2 * j + 0], a0A);
            a0B = ffma2(v.y, own[0][2 * j + 1], a0B);
            a1A = ffma2(v.x, own[1][2 * j + 0], a1A);
            a1B = ffma2(v.y, own[1][2 * j + 1], a1B);
        }
#pragma unroll
        for (int j = 0; j < 4; j++) {
            const ulonglong2 v = vR[j];
            a0A = ffma2(v.x, recv[0][2 * j + 0], a0A);
            a0B = ffma2(v.y, recv[0][2 * j + 1], a0B);
            a1A = ffma2(v.x, recv[1][2 * j + 0], a1A);
            a1B = ffma2(v.y, recv[1][2 * j + 1], a1B);
        }
        float2 r;
        {
            float2 fA = unpk2(a0A), fB = unpk2(a0B);
            r.x = (fA.x + fB.x) + (fA.y + fB.y);
        }
        {
            float2 fA = unpk2(a1A), fB = unpk2(a1B);
            r.y = (fA.x + fB.x) + (fA.y + fB.y);
        }
        *reinterpret_cast<float2*>(oa + (size_t)k * N_) = r;
    }
}

extern "C" void kernel_launch(void* const* d_in, const int* in_sizes, int n_in,
                              void* d_out, int out_size) {
    const float* wf   = (const float*)d_in[0];
    const float* img  = (const float*)d_in[1];
    const int*   msk  = (const int*)d_in[2];
    const float* Wm   = (const float*)d_in[3];
    const float* bias = (const float*)d_in[4];

    float* out_attn = (float*)d_out;
    float* out_coef = (float*)d_out + (size_t)B_ * DH_ * N_;

    dim3 vgrid(4, B_);
    values_kernel<<<vgrid, 256>>>(wf, Wm, bias);

    dim3 grid(N_ / 512, B_);
    attn_kernel<<<grid, 256>>>(img, msk, out_attn, out_coef);
}